// round 4
// baseline (speedup 1.0000x reference)
#include <cuda_runtime.h>
#include <cstdint>

// ---------------------------------------------------------------------------
// CropConvNeuralProcess: stride-2 3x3 conv, B=32, Cin=Cout=256, 64x64 -> 32x32.
// Crop mask is provably all-ones -> pure convolution.
//
// Implicit GEMM on mma.sync m16n8k8 tf32 (base-target PTX; tcgen05 rejected by
// the harness's compute_103 virtual arch).
//
// R4: L1-bound fix. Fragment-ordered A (prep kernel pre-permutes weights so
// cp.async lands fragments for single LDS.128 loads), fragment-friendly B
// layout (conflict-free scalar LDS + STS.64 stores), and N=256 per CTA to
// halve A fragment traffic per unit work.
//
//   CTA tile: M=128 (cout), N=256 (8 out rows x 32 cols), K=2304 in 72x32.
//   Grid = 32 images x 4 sp-tiles x 2 cout-tiles = 256 CTAs, 256 threads,
//   8 warps in 2x4, each warp 64x64 (acc[4][8][4] = 128 regs).
// ---------------------------------------------------------------------------

__device__ uint32_t g_Wt[2 * 72 * 4096];   // fragment-ordered tf32 weights

// SMEM (float indices)
static constexpr int A_FLOATS = 32 * 160;           // 5120 (32 blks x 160, padded)
static constexpr int B_FLOATS = 32 * 260;           // 8320 (32 rowblks x 260)
static constexpr int B_BASE   = 2 * A_FLOATS;       // 10240
static constexpr int SMEM_BYTES = (2 * A_FLOATS + 2 * B_FLOATS) * 4;  // 107520

// --------------------------- helpers ---------------------------------------

__device__ __forceinline__ uint32_t smem_u32(const void* p) {
    uint32_t a;
    asm("{ .reg .u64 t; cvta.to.shared.u64 t, %1; cvt.u32.u64 %0, t; }" : "=r"(a) : "l"(p));
    return a;
}

__device__ __forceinline__ uint32_t tf32r(float f) {
    uint32_t r;
    asm("cvt.rna.tf32.f32 %0, %1;" : "=r"(r) : "f"(f));
    return r;
}

__device__ __forceinline__ void cp_async16(uint32_t dst, const void* src) {
    asm volatile("cp.async.ca.shared.global [%0], [%1], 16;" :: "r"(dst), "l"(src));
}

__device__ __forceinline__ void mma_tf32(float* c, uint32_t a0, uint32_t a1,
                                         uint32_t a2, uint32_t a3,
                                         uint32_t b0, uint32_t b1) {
    asm volatile(
        "mma.sync.aligned.m16n8k8.row.col.f32.tf32.tf32.f32 "
        "{%0,%1,%2,%3}, {%4,%5,%6,%7}, {%8,%9}, {%0,%1,%2,%3};"
        : "+f"(c[0]), "+f"(c[1]), "+f"(c[2]), "+f"(c[3])
        : "r"(a0), "r"(a1), "r"(a2), "r"(a3), "r"(b0), "r"(b1));
}

// --------------------------- prep kernel -----------------------------------
// w[cout][cin][3][3] f32 -> g_Wt fragment-ordered tf32 bits.
// Layout: p = ((ct*72 + chunk)*1024 + cell)*4 + pos
//   cell = blk*32 + acol*8 + ar,  blk = (wm*4 + kc)*4 + mt,  pos = cs*2 + h
//   m   = wm*64 + mt*16 + h*8 + ar          (cout = ct*128 + m)
//   kk  = kc*8 + cs*4 + acol                (cin  = cb*32 + kk)
//   chunk = (kh*3+kw)*8 + cb
__global__ void __launch_bounds__(256) prep_kernel(const float* __restrict__ w) {
    int p = blockIdx.x * 256 + threadIdx.x;       // 589824 total
    int pos   = p & 3;
    int cell  = (p >> 2) & 1023;
    int ctch  = p >> 12;                          // ct*72 + chunk
    int ct    = ctch / 72;
    int chunk = ctch - ct * 72;

    int blk  = cell >> 5;
    int acol = (cell >> 3) & 3;
    int ar   = cell & 7;
    int wm   = blk >> 4;
    int kc   = (blk >> 2) & 3;
    int mt   = blk & 3;
    int cs   = pos >> 1;
    int h    = pos & 1;

    int m    = wm * 64 + mt * 16 + h * 8 + ar;
    int cout = ct * 128 + m;
    int kk   = kc * 8 + cs * 4 + acol;
    int tap  = chunk >> 3;
    int cb   = chunk & 7;
    int cin  = cb * 32 + kk;

    g_Wt[p] = tf32r(w[(size_t)(cout * 256 + cin) * 9 + tap]);
}

// --------------------------- main kernel -----------------------------------

__global__ void __launch_bounds__(256, 1) conv_kernel(const float* __restrict__ x,
                                                      float* __restrict__ out) {
    extern __shared__ float smf[];
    uint32_t* smu = reinterpret_cast<uint32_t*>(smf);
    const uint32_t smem_base = smem_u32(smf);

    const int tid  = threadIdx.x;
    const int lane = tid & 31;
    const int wid  = tid >> 5;
    const int warp_m = wid >> 2;        // 0..1 -> 64 couts
    const int warp_n = wid & 3;         // 0..3 -> 64 cols

    const int bid = blockIdx.x;         // 256 CTAs
    const int ct  = bid & 1;
    const int spt = (bid >> 1) & 3;
    const int b   = bid >> 3;
    const int cout0 = ct * 128;
    const int oh0   = spt * 8;          // 8 output rows per CTA

    const float* xb = x + (size_t)b * 256 * 4096;

    float acc[4][8][4];
#pragma unroll
    for (int i = 0; i < 4; i++)
#pragma unroll
        for (int j = 0; j < 8; j++)
#pragma unroll
            for (int k = 0; k < 4; k++) acc[i][j][k] = 0.f;

    float4 v[16];
    const int r  = tid >> 5;            // output row 0..7 (uniform per warp)
    const int j  = lane & 15;           // float4 pos along iw
    const int h2 = lane >> 4;           // cin parity

    // ---- im2col gather: 16 float4 per thread (one (kh, cb) row set) ----
    auto gather = [&](int c) {
        const int tap = c >> 3, cb = c & 7;
        const int kh  = tap / 3;
        const int ih  = 2 * (oh0 + r) + kh - 1;
        const float* rp = xb + ((size_t)(cb * 32) << 12) + (ih << 6) + (j << 2);
#pragma unroll
        for (int g = 0; g < 16; g++) {
            int cin2 = 2 * g + h2;
            if (ih >= 0)
                v[g] = *reinterpret_cast<const float4*>(rp + ((size_t)cin2 << 12));
            else
                v[g] = make_float4(0.f, 0.f, 0.f, 0.f);
        }
    };

    // ---- convert + store B tile in fragment layout ----
    // value (k, n) -> word boff + ((kc*4 + (k&3))*2 + ((k&7)>>2))*260 + n
    auto stsB = [&](int c, int boff) {
        const int tap = c >> 3;
        const int kw  = tap - (tap / 3) * 3;
#pragma unroll
        for (int g = 0; g < 16; g++) {
            int cin2 = 2 * g + h2;                 // k within chunk (0..31)
            int kc = cin2 >> 3, s = cin2 & 7;
            int base = boff + ((kc * 4 + (s & 3)) * 2 + (s >> 2)) * 260 + r * 32;
            float4 q = v[g];
            if (kw == 1) {                         // iw=2ow: x->ow=2j, z->2j+1
                *reinterpret_cast<uint2*>(&smu[base + 2 * j]) =
                    make_uint2(tf32r(q.x), tf32r(q.z));
            } else if (kw == 2) {                  // iw=2ow+1: y->2j, w->2j+1
                *reinterpret_cast<uint2*>(&smu[base + 2 * j]) =
                    make_uint2(tf32r(q.y), tf32r(q.w));
            } else {                               // kw=0: iw=2ow-1: y->2j+1, w->2j+2
                smu[base + 2 * j + 1] = tf32r(q.y);
                if (j < 15) smu[base + 2 * j + 2] = tf32r(q.w);
                if (j == 0) smu[base] = 0u;        // ow=0 reads iw=-1 padding
            }
        }
    };

    // ---- A tile: cp.async 4x16B per thread, fragment-ordered source ----
    auto cpA = [&](int c, int aoff) {
        const uint32_t* srcbase = &g_Wt[(((size_t)ct * 72 + c) << 10) << 2];
#pragma unroll
        for (int i = 0; i < 4; i++) {
            int cell = tid + (i << 8);
            int blk = cell >> 5, acol = (cell >> 3) & 3, ar = cell & 7;
            uint32_t dst = smem_base +
                (uint32_t)(aoff + blk * 160 + acol * 40 + ar * 4) * 4u;
            cp_async16(dst, srcbase + cell * 4);
        }
    };

    // ---- MMA over one 32-K chunk ----
    auto domma = [&](int aoff, int boff) {
        const int ar2  = lane >> 2;     // 0..7
        const int acol = lane & 3;      // 0..3
#pragma unroll
        for (int kc = 0; kc < 4; kc++) {
            uint32_t bf[8][2];
            const int rb = boff + (kc * 4 + acol) * 2 * 260 + warp_n * 64 + ar2;
#pragma unroll
            for (int nt = 0; nt < 8; nt++) {
                bf[nt][0] = smu[rb + nt * 8];
                bf[nt][1] = smu[rb + 260 + nt * 8];
            }
#pragma unroll
            for (int mt = 0; mt < 4; mt++) {
                const int blk = (warp_m * 4 + kc) * 4 + mt;
                uint4 av = *reinterpret_cast<const uint4*>(
                    &smu[aoff + blk * 160 + acol * 40 + ar2 * 4]);
#pragma unroll
                for (int nt = 0; nt < 8; nt++)
                    mma_tf32(acc[mt][nt], av.x, av.y, av.z, av.w,
                             bf[nt][0], bf[nt][1]);
            }
        }
    };

    // chunk order: kh outer, cin-block mid, kw inner (L1 reuse of input rows)
    auto chunk_of = [](int it) {
        int kh = it / 24, rem = it - kh * 24;
        int cb = rem / 3, kw = rem - cb * 3;
        return (kh * 3 + kw) * 8 + cb;
    };

    // ---- prologue ----
    {
        int c0 = chunk_of(0);
        gather(c0);
        cpA(c0, 0);
        asm volatile("cp.async.commit_group;" ::: "memory");
        stsB(c0, B_BASE);
    }

    // ---- main loop ----
    for (int it = 0; it < 72; it++) {
        const int buf   = it & 1;
        const int aoff  = buf * A_FLOATS;
        const int boff  = B_BASE + buf * B_FLOATS;
        const int naoff = (buf ^ 1) * A_FLOATS;
        const int nboff = B_BASE + (buf ^ 1) * B_FLOATS;
        const bool more = (it + 1 < 72);

        asm volatile("cp.async.wait_group 0;" ::: "memory");
        __syncthreads();                           // buffers(it) fully visible

        if (more) {
            int cn = chunk_of(it + 1);
            gather(cn);                            // LDGs fly during domma
            cpA(cn, naoff);
            asm volatile("cp.async.commit_group;" ::: "memory");
        }

        domma(aoff, boff);

        if (more) stsB(chunk_of(it + 1), nboff);
    }

    // ---- epilogue: direct STG.64 ----
    const size_t outbase = ((size_t)(b * 256 + cout0)) * 1024 + spt * 256;
#pragma unroll
    for (int mt = 0; mt < 4; mt++) {
#pragma unroll
        for (int nt = 0; nt < 8; nt++) {
            int m = warp_m * 64 + mt * 16 + (lane >> 2);
            int n = warp_n * 64 + nt * 8 + 2 * (lane & 3);
            *reinterpret_cast<float2*>(&out[outbase + (size_t)m * 1024 + n]) =
                make_float2(acc[mt][nt][0], acc[mt][nt][1]);
            *reinterpret_cast<float2*>(&out[outbase + (size_t)(m + 8) * 1024 + n]) =
                make_float2(acc[mt][nt][2], acc[mt][nt][3]);
        }
    }
}

// --------------------------- launch ----------------------------------------
extern "C" void kernel_launch(void* const* d_in, const int* in_sizes, int n_in,
                              void* d_out, int out_size) {
    const float* x = (const float*)d_in[0];
    const float* w = (const float*)d_in[1];
    float* out = (float*)d_out;
    (void)in_sizes; (void)n_in; (void)out_size;

    prep_kernel<<<2304, 256>>>(w);

    cudaFuncSetAttribute(conv_kernel, cudaFuncAttributeMaxDynamicSharedMemorySize, SMEM_BYTES);
    conv_kernel<<<256, 256, SMEM_BYTES>>>(x, out);
}

// round 9
// speedup vs baseline: 1.0488x; 1.0488x over previous
#include <cuda_runtime.h>
#include <cuda_fp16.h>
#include <cstdint>

// ---------------------------------------------------------------------------
// CropConvNeuralProcess: stride-2 3x3 conv, B=32, Cin=Cout=256, 64x64 -> 32x32.
// Crop mask is provably all-ones -> pure convolution.
//
// R5: legacy mma.sync m16n8k16 FP16 (f32 accumulate). fp16 has the same
// 10-bit mantissa as tf32 (R3/R4 measured rel_err 2.9e-4) but the legacy
// HMMA f16 path runs at 2x the tf32 rate. Fragment-ordered A (one LDS.128
// per fragment), k-pair-packed B (conflict-free scalar LDS, STS.128 stores).
//
//   CTA tile: M=128 (cout), N=128 (4 out rows x 32 cols), K=2304 in 72x32.
//   Grid = 32 images x 8 sp-tiles x 2 cout-tiles = 512 CTAs, 256 threads,
//   8 warps 2x4, warp tile 64x32, acc[4][4][4] = 64 regs.
// ---------------------------------------------------------------------------

__device__ uint32_t g_Wf[2 * 72 * 2048];   // fragment-ordered f16x2 weights

// SMEM word (u32) layout
static constexpr int A_WORDS = 2048;                 // 128 x 32 f16 = 8KB
static constexpr int B_PITCH = 136;                  // words per k-pair row
static constexpr int B_WORDS = 16 * B_PITCH;         // 2176
static constexpr int B_BASE  = 2 * A_WORDS;          // 4096
static constexpr int SMEM_BYTES = (2 * A_WORDS + 2 * B_WORDS) * 4;  // 33792

// --------------------------- helpers ---------------------------------------

__device__ __forceinline__ uint32_t smem_u32(const void* p) {
    uint32_t a;
    asm("{ .reg .u64 t; cvta.to.shared.u64 t, %1; cvt.u32.u64 %0, t; }" : "=r"(a) : "l"(p));
    return a;
}

// pack two f32 -> f16x2 word: lo = e (even cin), hi = o (odd cin)
__device__ __forceinline__ uint32_t pack_h2(float e, float o) {
    uint32_t r;
    asm("cvt.rn.f16x2.f32 %0, %1, %2;" : "=r"(r) : "f"(o), "f"(e));
    return r;
}

__device__ __forceinline__ void cp_async16(uint32_t dst, const void* src) {
    asm volatile("cp.async.ca.shared.global [%0], [%1], 16;" :: "r"(dst), "l"(src));
}

__device__ __forceinline__ void mma_f16(float* c, uint32_t a0, uint32_t a1,
                                        uint32_t a2, uint32_t a3,
                                        uint32_t b0, uint32_t b1) {
    asm volatile(
        "mma.sync.aligned.m16n8k16.row.col.f32.f16.f16.f32 "
        "{%0,%1,%2,%3}, {%4,%5,%6,%7}, {%8,%9}, {%0,%1,%2,%3};"
        : "+f"(c[0]), "+f"(c[1]), "+f"(c[2]), "+f"(c[3])
        : "r"(a0), "r"(a1), "r"(a2), "r"(a3), "r"(b0), "r"(b1));
}

// --------------------------- prep kernel -----------------------------------
// w[cout][cin][3][3] f32 -> g_Wf fragment-ordered f16x2.
// word index p = (((ct*72+chunk)*16 + tile)*32 + lane)*4 + pos
//   tile = wm*8 + kc*4 + mt      (wm 0..1, kc 0..1, mt 0..3)
//   m  = wm*64 + mt*16 + (pos&1)*8 + (lane>>2)
//   k2 = kc*16 + ((pos>>1)&1)*8 + 2*(lane&3)   (f16 pair k2, k2+1)
//   cout = ct*128 + m;  cin = (chunk&7)*32 + k2;  tap = chunk>>3
__global__ void __launch_bounds__(256) prep_kernel(const float* __restrict__ w) {
    int p = blockIdx.x * 256 + threadIdx.x;        // 294912 total
    int pos  = p & 3;
    int lane = (p >> 2) & 31;
    int tile = (p >> 7) & 15;
    int ctch = p >> 11;
    int ct    = ctch / 72;
    int chunk = ctch - ct * 72;

    int wm = tile >> 3, kc = (tile >> 2) & 1, mt = tile & 3;
    int m  = wm * 64 + mt * 16 + ((pos & 1) << 3) + (lane >> 2);
    int k2 = kc * 16 + ((pos >> 1) & 1) * 8 + 2 * (lane & 3);
    int cout = ct * 128 + m;
    int tap  = chunk >> 3;
    int cin  = (chunk & 7) * 32 + k2;

    float we = w[(size_t)(cout * 256 + cin) * 9 + tap];
    float wo = w[(size_t)(cout * 256 + cin + 1) * 9 + tap];
    g_Wf[p] = pack_h2(we, wo);
}

// --------------------------- main kernel -----------------------------------

__global__ void __launch_bounds__(256, 2) conv_kernel(const float* __restrict__ x,
                                                      float* __restrict__ out) {
    extern __shared__ float smf[];
    uint32_t* smu = reinterpret_cast<uint32_t*>(smf);
    const uint32_t smem_base = smem_u32(smf);

    const int tid  = threadIdx.x;
    const int lane = tid & 31;
    const int wid  = tid >> 5;
    const int warp_m = wid >> 2;        // 0..1 -> 64 couts
    const int warp_n = wid & 3;         // 0..3 -> 32 cols

    const int bid = blockIdx.x;         // 512 CTAs
    const int ct  = bid & 1;
    const int spt = (bid >> 1) & 7;
    const int b   = bid >> 4;
    const int cout0 = ct * 128;
    const int oh0   = spt * 4;          // 4 output rows per CTA

    const float* xb = x + (size_t)b * 256 * 4096;

    float acc[4][4][4];
#pragma unroll
    for (int i = 0; i < 4; i++)
#pragma unroll
        for (int j = 0; j < 4; j++)
#pragma unroll
            for (int k = 0; k < 4; k++) acc[i][j][k] = 0.f;

    // gather decomposition: kp = cin-pair (0..15), r = out row (0..3), jj = iw/16
    const int kp = tid >> 4;
    const int r  = (tid >> 2) & 3;
    const int jj = tid & 3;

    float4 ve[4], vo[4];

    // ---- im2col gather: 8 LDG.128 (two adjacent cin planes, 16 iw each) ----
    auto gather = [&](int c) {
        const int tap = c >> 3, cb = c & 7;
        const int kh  = tap / 3;
        const int ih  = 2 * (oh0 + r) + kh - 1;
        const float* pe = xb + (((size_t)(cb * 32 + 2 * kp)) << 12) + (ih << 6) + jj * 16;
#pragma unroll
        for (int t = 0; t < 4; t++) {
            if (ih >= 0) {
                ve[t] = *reinterpret_cast<const float4*>(pe + 4 * t);
                vo[t] = *reinterpret_cast<const float4*>(pe + 4096 + 4 * t);
            } else {
                ve[t] = make_float4(0.f, 0.f, 0.f, 0.f);
                vo[t] = make_float4(0.f, 0.f, 0.f, 0.f);
            }
        }
    };

    // ---- convert + store B: word (kp, n=r*32+ow) at boff + kp*136 + n ----
    auto stsB = [&](int c, int boff) {
        const int tap = c >> 3;
        const int kw  = tap - (tap / 3) * 3;
        const int base = boff + kp * B_PITCH + r * 32;
        if (kw == 1) {                       // iw=2ow: x -> ow=2t, z -> 2t+1
            uint32_t ww[8];
#pragma unroll
            for (int t = 0; t < 4; t++) {
                ww[2 * t]     = pack_h2(ve[t].x, vo[t].x);
                ww[2 * t + 1] = pack_h2(ve[t].z, vo[t].z);
            }
            *reinterpret_cast<uint4*>(&smu[base + 8 * jj]) =
                make_uint4(ww[0], ww[1], ww[2], ww[3]);
            *reinterpret_cast<uint4*>(&smu[base + 8 * jj + 4]) =
                make_uint4(ww[4], ww[5], ww[6], ww[7]);
        } else if (kw == 2) {                // iw=2ow+1: y -> 2t, w -> 2t+1
            uint32_t ww[8];
#pragma unroll
            for (int t = 0; t < 4; t++) {
                ww[2 * t]     = pack_h2(ve[t].y, vo[t].y);
                ww[2 * t + 1] = pack_h2(ve[t].w, vo[t].w);
            }
            *reinterpret_cast<uint4*>(&smu[base + 8 * jj]) =
                make_uint4(ww[0], ww[1], ww[2], ww[3]);
            *reinterpret_cast<uint4*>(&smu[base + 8 * jj + 4]) =
                make_uint4(ww[4], ww[5], ww[6], ww[7]);
        } else {                             // kw=0: iw=2ow-1: y->2t+1, w->2t+2
#pragma unroll
            for (int t = 0; t < 4; t++) {
                smu[base + 8 * jj + 2 * t + 1] = pack_h2(ve[t].y, vo[t].y);
                if (!(jj == 3 && t == 3))
                    smu[base + 8 * jj + 2 * t + 2] = pack_h2(ve[t].w, vo[t].w);
            }
            if (jj == 0) smu[base] = 0u;     // ow=0 reads iw=-1 padding
        }
    };

    // ---- A tile: 2 cp.async16 per thread, fragment-ordered source ----
    auto cpA = [&](int c, int aoff) {
        const uint32_t* src = &g_Wf[((size_t)(ct * 72 + c)) << 11];
        uint32_t dst = smem_base + (uint32_t)(aoff + tid * 8) * 4u;
        cp_async16(dst, src + tid * 8);
        cp_async16(dst + 16, src + tid * 8 + 4);
    };

    // ---- MMA over one 32-K chunk: 2 kc x 4 mt x 4 nt m16n8k16 ----
    auto domma = [&](int aoff, int boff) {
        const int rr = lane >> 2;       // 0..7
        const int cc = lane & 3;        // 0..3
#pragma unroll
        for (int kc = 0; kc < 2; kc++) {
            uint32_t bf[4][2];
            const int rb = boff + (kc * 8 + cc) * B_PITCH + warp_n * 32 + rr;
#pragma unroll
            for (int nt = 0; nt < 4; nt++) {
                bf[nt][0] = smu[rb + nt * 8];
                bf[nt][1] = smu[rb + 4 * B_PITCH + nt * 8];
            }
#pragma unroll
            for (int mt = 0; mt < 4; mt++) {
                const int tile = warp_m * 8 + kc * 4 + mt;
                uint4 av = *reinterpret_cast<const uint4*>(
                    &smu[aoff + tile * 128 + lane * 4]);
#pragma unroll
                for (int nt = 0; nt < 4; nt++)
                    mma_f16(acc[mt][nt], av.x, av.y, av.z, av.w,
                            bf[nt][0], bf[nt][1]);
            }
        }
    };

    // chunk order: kh outer, cin-block mid, kw inner (L1 reuse of input rows)
    auto chunk_of = [](int it) {
        int kh = it / 24, rem = it - kh * 24;
        int cb = rem / 3, kw = rem - cb * 3;
        return (kh * 3 + kw) * 8 + cb;
    };

    // ---- prologue ----
    {
        int c0 = chunk_of(0);
        gather(c0);
        cpA(c0, 0);
        asm volatile("cp.async.commit_group;" ::: "memory");
        stsB(c0, B_BASE);
    }

    // ---- main loop ----
    for (int it = 0; it < 72; it++) {
        const int buf   = it & 1;
        const int aoff  = buf * A_WORDS;
        const int boff  = B_BASE + buf * B_WORDS;
        const int naoff = (buf ^ 1) * A_WORDS;
        const int nboff = B_BASE + (buf ^ 1) * B_WORDS;
        const bool more = (it + 1 < 72);

        asm volatile("cp.async.wait_group 0;" ::: "memory");
        __syncthreads();                            // buffers(it) visible

        if (more) {
            int cn = chunk_of(it + 1);
            gather(cn);                             // LDGs fly during domma
            cpA(cn, naoff);
            asm volatile("cp.async.commit_group;" ::: "memory");
        }

        domma(aoff, boff);

        if (more) stsB(chunk_of(it + 1), nboff);
    }

    // ---- epilogue: direct STG.64 ----
    const size_t outbase = ((size_t)(b * 256 + cout0)) * 1024 + spt * 128;
#pragma unroll
    for (int mt = 0; mt < 4; mt++) {
#pragma unroll
        for (int nt = 0; nt < 4; nt++) {
            int m = warp_m * 64 + mt * 16 + (lane >> 2);
            int n = warp_n * 32 + nt * 8 + 2 * (lane & 3);
            *reinterpret_cast<float2*>(&out[outbase + (size_t)m * 1024 + n]) =
                make_float2(acc[mt][nt][0], acc[mt][nt][1]);
            *reinterpret_cast<float2*>(&out[outbase + (size_t)(m + 8) * 1024 + n]) =
                make_float2(acc[mt][nt][2], acc[mt][nt][3]);
        }
    }
}

// --------------------------- launch ----------------------------------------
extern "C" void kernel_launch(void* const* d_in, const int* in_sizes, int n_in,
                              void* d_out, int out_size) {
    const float* x = (const float*)d_in[0];
    const float* w = (const float*)d_in[1];
    float* out = (float*)d_out;
    (void)in_sizes; (void)n_in; (void)out_size;

    prep_kernel<<<1152, 256>>>(w);

    cudaFuncSetAttribute(conv_kernel, cudaFuncAttributeMaxDynamicSharedMemorySize, SMEM_BYTES);
    conv_kernel<<<512, 256, SMEM_BYTES>>>(x, out);
}